// round 3
// baseline (speedup 1.0000x reference)
#include <cuda_runtime.h>
#include <math.h>
#include <stdint.h>

// Problem dims
constexpr int kT  = 4096;   // timesteps
constexpr int kD  = 1024;   // input dim
constexpr int kH  = 2048;   // hidden
constexpr int kH3 = 3 * kH; // 6144

// -------- scratch (static device globals; no allocation allowed) --------
__device__ float g_xp[2][(size_t)kT * kH3];   // precomputed input projections, 2x100.7MB
__device__ float g_h[2][2][kH];               // ping-pong hidden state [buf][gru][H]
__device__ unsigned g_bar_count;              // barrier arrival counter (self-resetting)
__device__ unsigned g_bar_gen;                // barrier generation (monotonic, wraps fine)

// ---------------- grid-wide barrier (non-cooperative, graph-safe) ----------------
__device__ __forceinline__ void grid_barrier(unsigned nblk)
{
    __syncthreads();
    if (threadIdx.x == 0) {
        __threadfence();   // publish this block's writes
        unsigned gen = *(volatile unsigned*)&g_bar_gen;
        unsigned arr = atomicAdd(&g_bar_count, 1u);
        if (arr == nblk - 1u) {
            g_bar_count = 0;
            __threadfence();
            atomicAdd(&g_bar_gen, 1u);   // release
        } else {
            while (*(volatile unsigned*)&g_bar_gen == gen) { __nanosleep(64); }
        }
        __threadfence();   // acquire other blocks' writes
    }
    __syncthreads();
}

// ---------------- Phase A: xp = x @ W_ih^T + b_ih  (both GRUs, z-dim) ----------------
constexpr int BM = 64, BN = 64, BK = 16;

__global__ void gemm_xp(const float* __restrict__ x1, const float* __restrict__ x2,
                        const float* __restrict__ Wih1, const float* __restrict__ Wih2,
                        const float* __restrict__ bih1, const float* __restrict__ bih2)
{
    const int gru = blockIdx.z;
    const float* __restrict__ x = gru ? x2 : x1;
    const float* __restrict__ W = gru ? Wih2 : Wih1;
    const float* __restrict__ b = gru ? bih2 : bih1;
    float* __restrict__ xp = g_xp[gru];

    __shared__ float As[BK][BM];
    __shared__ float Bs[BK][BN];

    const int t0 = blockIdx.y * BM;
    const int j0 = blockIdx.x * BN;
    const int tid = threadIdx.x;          // 256 threads
    const int tx = tid & 15, ty = tid >> 4;
    const int lrow = tid >> 2;            // 0..63
    const int lk4  = (tid & 3) * 4;       // 0,4,8,12

    float acc[4][4] = {};

    for (int k0 = 0; k0 < kD; k0 += BK) {
        float4 av = *(const float4*)(x + (size_t)(t0 + lrow) * kD + k0 + lk4);
        float4 bv = *(const float4*)(W + (size_t)(j0 + lrow) * kD + k0 + lk4);
        As[lk4 + 0][lrow] = av.x; As[lk4 + 1][lrow] = av.y;
        As[lk4 + 2][lrow] = av.z; As[lk4 + 3][lrow] = av.w;
        Bs[lk4 + 0][lrow] = bv.x; Bs[lk4 + 1][lrow] = bv.y;
        Bs[lk4 + 2][lrow] = bv.z; Bs[lk4 + 3][lrow] = bv.w;
        __syncthreads();
        #pragma unroll
        for (int kk = 0; kk < BK; kk++) {
            float a[4], c[4];
            #pragma unroll
            for (int i = 0; i < 4; i++) a[i] = As[kk][ty * 4 + i];
            #pragma unroll
            for (int j = 0; j < 4; j++) c[j] = Bs[kk][tx * 4 + j];
            #pragma unroll
            for (int i = 0; i < 4; i++)
                #pragma unroll
                for (int j = 0; j < 4; j++)
                    acc[i][j] = fmaf(a[i], c[j], acc[i][j]);
        }
        __syncthreads();
    }

    const int jj0 = j0 + tx * 4;
    float b0 = b[jj0], b1 = b[jj0 + 1], b2 = b[jj0 + 2], b3 = b[jj0 + 3];
    #pragma unroll
    for (int i = 0; i < 4; i++) {
        float4 v = make_float4(acc[i][0] + b0, acc[i][1] + b1,
                               acc[i][2] + b2, acc[i][3] + b3);
        // streaming store: xp is read exactly once later; keep L2 for W_hh
        __stcs((float4*)(xp + (size_t)(t0 + ty * 4 + i) * kH3 + jj0), v);
    }
}

// ---------------- Phase B: persistent GRU recurrence ----------------
// grid = 128 blocks (<= SM count -> co-resident, barrier-safe), 1024 threads.
// Block b: gru = b/64, owns 32 hidden indices jbase..jbase+31. Warp w handles j = jbase+w,
// computing all 3 gate dot-products so the gate math needs no inter-warp exchange.
__global__ void __launch_bounds__(1024, 1) gru_seq(
    const float* __restrict__ Whh1, const float* __restrict__ Whh2,
    const float* __restrict__ bhh1, const float* __restrict__ bhh2)
{
    const int blk = blockIdx.x;       // 0..127
    const int gru = blk >> 6;
    const int jbase = (blk & 63) * 32;
    const float* __restrict__ W   = gru ? Whh2 : Whh1;
    const float* __restrict__ bhh = gru ? bhh2 : bhh1;
    const float* __restrict__ xp  = g_xp[gru];

    const int tid = threadIdx.x;
    const int w = tid >> 5, lane = tid & 31;
    const int j = jbase + w;

    __shared__ float sh[kH];

    // init h0 = 0 (this block's slice)
    if (tid < 32) g_h[0][gru][jbase + tid] = 0.f;

    const float br = bhh[j], bz = bhh[kH + j], bn = bhh[2 * kH + j];
    const float4* __restrict__ wr = (const float4*)(W + (size_t)j * kH);
    const float4* __restrict__ wz = (const float4*)(W + (size_t)(kH + j) * kH);
    const float4* __restrict__ wn = (const float4*)(W + (size_t)(2 * kH + j) * kH);

    const unsigned nblk = gridDim.x;
    grid_barrier(nblk);

    for (int t = 0; t < kT; t++) {
        const int cur = t & 1, nxt = cur ^ 1;

        // stage h into smem (2048 floats, 1024 threads x2)
        sh[tid]        = g_h[cur][gru][tid];
        sh[tid + 1024] = g_h[cur][gru][tid + 1024];
        __syncthreads();

        // prefetch this step's input projections (lane 0 only needs them)
        float xr = 0.f, xz = 0.f, xn = 0.f;
        if (lane == 0) {
            const float* xpt = xp + (size_t)t * kH3;
            xr = __ldcs(xpt + j);
            xz = __ldcs(xpt + kH + j);
            xn = __ldcs(xpt + 2 * kH + j);
        }

        float sr = 0.f, sz = 0.f, sn = 0.f;
        const float4* hv = (const float4*)sh;
        #pragma unroll 4
        for (int i = lane; i < kH / 4; i += 32) {
            float4 h4 = hv[i];
            float4 a = wr[i], c = wz[i], d = wn[i];
            sr = fmaf(a.x, h4.x, sr); sr = fmaf(a.y, h4.y, sr);
            sr = fmaf(a.z, h4.z, sr); sr = fmaf(a.w, h4.w, sr);
            sz = fmaf(c.x, h4.x, sz); sz = fmaf(c.y, h4.y, sz);
            sz = fmaf(c.z, h4.z, sz); sz = fmaf(c.w, h4.w, sz);
            sn = fmaf(d.x, h4.x, sn); sn = fmaf(d.y, h4.y, sn);
            sn = fmaf(d.z, h4.z, sn); sn = fmaf(d.w, h4.w, sn);
        }
        #pragma unroll
        for (int off = 16; off; off >>= 1) {
            sr += __shfl_down_sync(0xffffffffu, sr, off);
            sz += __shfl_down_sync(0xffffffffu, sz, off);
            sn += __shfl_down_sync(0xffffffffu, sn, off);
        }

        if (lane == 0) {
            float hr = sr + br, hz = sz + bz, hn = sn + bn;
            float r = 1.f / (1.f + expf(-(xr + hr)));
            float z = 1.f / (1.f + expf(-(xz + hz)));
            float n = tanhf(xn + r * hn);
            g_h[nxt][gru][j] = (1.f - z) * n + z * sh[j];
        }

        grid_barrier(nblk);   // includes __syncthreads on entry (protects sh reuse)
    }
    // final h lands in g_h[0] (t=4095: cur=1 -> nxt=0)
}

// ---------------- Phase C: MLP head + log_softmax ----------------
__global__ void head_kernel(const float* __restrict__ fc1_w, const float* __restrict__ fc1_b,
                            const float* __restrict__ fc2_w, const float* __restrict__ fc2_b,
                            float* __restrict__ out)
{
    __shared__ float partial[256][4];
    __shared__ float act[256];
    __shared__ float logits[3];

    const int tid = threadIdx.x;       // 1024 threads
    const int row = tid >> 2, part = tid & 3;

    // concat = [h1(2048), h2(2048)]; part p covers k in [p*1024, p*1024+1024)
    const float* hsrc = (part < 2) ? &g_h[0][0][(part & 1) * 1024]
                                   : &g_h[0][1][(part & 1) * 1024];
    const float4* wv = (const float4*)(fc1_w + (size_t)row * (2 * kH) + part * 1024);
    const float4* hv = (const float4*)hsrc;

    float s = 0.f;
    #pragma unroll 4
    for (int i = 0; i < 256; i++) {
        float4 a = wv[i], h4 = hv[i];
        s = fmaf(a.x, h4.x, s); s = fmaf(a.y, h4.y, s);
        s = fmaf(a.z, h4.z, s); s = fmaf(a.w, h4.w, s);
    }
    partial[row][part] = s;
    __syncthreads();

    if (tid < 256) {
        float v = partial[tid][0] + partial[tid][1] + partial[tid][2] + partial[tid][3]
                + fc1_b[tid];
        act[tid] = fmaxf(v, 0.f);
    }
    __syncthreads();

    if (tid < 3) {
        float s2 = fc2_b[tid];
        for (int k = 0; k < 256; k++) s2 = fmaf(fc2_w[tid * 256 + k], act[k], s2);
        logits[tid] = s2;
    }
    __syncthreads();

    if (tid == 0) {
        float m = fmaxf(logits[0], fmaxf(logits[1], logits[2]));
        float lse = m + logf(expf(logits[0] - m) + expf(logits[1] - m) + expf(logits[2] - m));
        out[0] = logits[0] - lse;
        out[1] = logits[1] - lse;
        out[2] = logits[2] - lse;
    }
}

// ---------------- launch ----------------
extern "C" void kernel_launch(void* const* d_in, const int* in_sizes, int n_in,
                              void* d_out, int out_size)
{
    const float* x1   = (const float*)d_in[0];
    const float* x2   = (const float*)d_in[1];
    const float* Wih1 = (const float*)d_in[2];
    const float* Whh1 = (const float*)d_in[3];
    const float* bih1 = (const float*)d_in[4];
    const float* bhh1 = (const float*)d_in[5];
    const float* Wih2 = (const float*)d_in[6];
    const float* Whh2 = (const float*)d_in[7];
    const float* bih2 = (const float*)d_in[8];
    const float* bhh2 = (const float*)d_in[9];
    const float* fc1w = (const float*)d_in[10];
    const float* fc1b = (const float*)d_in[11];
    const float* fc2w = (const float*)d_in[12];
    const float* fc2b = (const float*)d_in[13];
    float* out = (float*)d_out;

    dim3 gA(kH3 / BN, kT / BM, 2);           // 96 x 64 x 2 blocks
    gemm_xp<<<gA, 256>>>(x1, x2, Wih1, Wih2, bih1, bih2);
    gru_seq<<<128, 1024>>>(Whh1, Whh2, bhh1, bhh2);
    head_kernel<<<1, 1024>>>(fc1w, fc1b, fc2w, fc2b, out);
}

// round 4
// speedup vs baseline: 1.6801x; 1.6801x over previous
#include <cuda_runtime.h>
#include <cuda_fp16.h>
#include <math.h>
#include <stdint.h>

// Problem dims
constexpr int kT  = 4096;   // timesteps
constexpr int kD  = 1024;   // input dim
constexpr int kH  = 2048;   // hidden
constexpr int kH3 = 3 * kH; // 6144

// GRU recurrence kernel config
constexpr int NCACHE = 18;                              // j's per block whose rows live in smem
constexpr int SMEM_BYTES = kH * 4 + NCACHE * 3 * kH * 2; // 8 KB h + 216 KB fp16 weights = 229376

// -------- scratch (static device globals; no allocation allowed) --------
__device__ float  g_xp[2][(size_t)kT * kH3];   // precomputed input projections
__device__ __half g_w16[2][(size_t)kH3 * kH];  // fp16 copy of W_hh (50.3 MB)
__device__ float  g_h[2][2][kH];               // ping-pong hidden state [buf][gru][H]
__device__ unsigned g_bar_count[2];            // per-GRU barrier counters
__device__ unsigned g_bar_gen[2];

// ---------------- per-GRU grid barrier (64 blocks, non-cooperative, graph-safe) ------
__device__ __forceinline__ void grid_barrier(int gru, unsigned nblk)
{
    __syncthreads();
    if (threadIdx.x == 0) {
        __threadfence();   // publish this block's writes
        unsigned gen = *(volatile unsigned*)&g_bar_gen[gru];
        unsigned arr = atomicAdd(&g_bar_count[gru], 1u);
        if (arr == nblk - 1u) {
            g_bar_count[gru] = 0;
            __threadfence();
            atomicAdd(&g_bar_gen[gru], 1u);   // release
        } else {
            while (*(volatile unsigned*)&g_bar_gen[gru] == gen) { __nanosleep(32); }
        }
        __threadfence();   // acquire other blocks' writes
    }
    __syncthreads();
}

// ---------------- W_hh fp32 -> fp16 conversion (round-to-nearest) ----------------
__global__ void convert_whh(const float* __restrict__ W1, const float* __restrict__ W2)
{
    const size_t i = (size_t)blockIdx.x * blockDim.x + threadIdx.x;   // over kH3*kH/2 pairs
    const float2* __restrict__ src = (const float2*)(blockIdx.y ? W2 : W1);
    __half2* __restrict__ dst = (__half2*)g_w16[blockIdx.y];
    float2 v = src[i];
    dst[i] = __floats2half2_rn(v.x, v.y);
}

// ---------------- Phase A: xp = x @ W_ih^T + b_ih (both GRUs, z-dim) ----------------
constexpr int BM = 64, BN = 64, BK = 16;

__global__ void gemm_xp(const float* __restrict__ x1, const float* __restrict__ x2,
                        const float* __restrict__ Wih1, const float* __restrict__ Wih2,
                        const float* __restrict__ bih1, const float* __restrict__ bih2)
{
    const int gru = blockIdx.z;
    const float* __restrict__ x = gru ? x2 : x1;
    const float* __restrict__ W = gru ? Wih2 : Wih1;
    const float* __restrict__ b = gru ? bih2 : bih1;
    float* __restrict__ xp = g_xp[gru];

    __shared__ float As[BK][BM];
    __shared__ float Bs[BK][BN];

    const int t0 = blockIdx.y * BM;
    const int j0 = blockIdx.x * BN;
    const int tid = threadIdx.x;          // 256 threads
    const int tx = tid & 15, ty = tid >> 4;
    const int lrow = tid >> 2;            // 0..63
    const int lk4  = (tid & 3) * 4;       // 0,4,8,12

    float acc[4][4] = {};

    for (int k0 = 0; k0 < kD; k0 += BK) {
        float4 av = *(const float4*)(x + (size_t)(t0 + lrow) * kD + k0 + lk4);
        float4 bv = *(const float4*)(W + (size_t)(j0 + lrow) * kD + k0 + lk4);
        As[lk4 + 0][lrow] = av.x; As[lk4 + 1][lrow] = av.y;
        As[lk4 + 2][lrow] = av.z; As[lk4 + 3][lrow] = av.w;
        Bs[lk4 + 0][lrow] = bv.x; Bs[lk4 + 1][lrow] = bv.y;
        Bs[lk4 + 2][lrow] = bv.z; Bs[lk4 + 3][lrow] = bv.w;
        __syncthreads();
        #pragma unroll
        for (int kk = 0; kk < BK; kk++) {
            float a[4], c[4];
            #pragma unroll
            for (int i = 0; i < 4; i++) a[i] = As[kk][ty * 4 + i];
            #pragma unroll
            for (int j = 0; j < 4; j++) c[j] = Bs[kk][tx * 4 + j];
            #pragma unroll
            for (int i = 0; i < 4; i++)
                #pragma unroll
                for (int j = 0; j < 4; j++)
                    acc[i][j] = fmaf(a[i], c[j], acc[i][j]);
        }
        __syncthreads();
    }

    const int jj0 = j0 + tx * 4;
    float b0 = b[jj0], b1 = b[jj0 + 1], b2 = b[jj0 + 2], b3 = b[jj0 + 3];
    #pragma unroll
    for (int i = 0; i < 4; i++) {
        float4 v = make_float4(acc[i][0] + b0, acc[i][1] + b1,
                               acc[i][2] + b2, acc[i][3] + b3);
        __stcs((float4*)(xp + (size_t)(t0 + ty * 4 + i) * kH3 + jj0), v);
    }
}

// ---------------- fp16 triple-row dot over full h (warp-collective) ----------------
// Element order: per iter i, lane l handles elements k = i*128 + l*4 .. +3.
// h loaded as float4 from smem (conflict-free), weights as uint2 (4 halves).
__device__ __forceinline__ void dot3(const uint2* __restrict__ wr,
                                     const uint2* __restrict__ wz,
                                     const uint2* __restrict__ wn,
                                     const float* __restrict__ sh_h,
                                     int lane, float& sr, float& sz, float& sn)
{
    const float4* __restrict__ hv = (const float4*)sh_h;
    #pragma unroll 4
    for (int i = 0; i < kH / 128; i++) {        // 16 iters
        const int idx = i * 32 + lane;
        float4 h4 = hv[idx];
        uint2 a = wr[idx], c = wz[idx], d = wn[idx];
        {
            float2 f0 = __half22float2(*(const __half2*)&a.x);
            float2 f1 = __half22float2(*(const __half2*)&a.y);
            sr = fmaf(f0.x, h4.x, sr); sr = fmaf(f0.y, h4.y, sr);
            sr = fmaf(f1.x, h4.z, sr); sr = fmaf(f1.y, h4.w, sr);
        }
        {
            float2 f0 = __half22float2(*(const __half2*)&c.x);
            float2 f1 = __half22float2(*(const __half2*)&c.y);
            sz = fmaf(f0.x, h4.x, sz); sz = fmaf(f0.y, h4.y, sz);
            sz = fmaf(f1.x, h4.z, sz); sz = fmaf(f1.y, h4.w, sz);
        }
        {
            float2 f0 = __half22float2(*(const __half2*)&d.x);
            float2 f1 = __half22float2(*(const __half2*)&d.y);
            sn = fmaf(f0.x, h4.x, sn); sn = fmaf(f0.y, h4.y, sn);
            sn = fmaf(f1.x, h4.z, sn); sn = fmaf(f1.y, h4.w, sn);
        }
    }
}

// ---------------- Phase B: persistent GRU recurrence ----------------
// 128 blocks x 1024 threads, block owns 32 hidden units, warp w owns j = jbase + w.
// Warps 0..NCACHE-1 read their 3 rows from smem; the rest stream fp16 rows from L2.
__global__ void __launch_bounds__(1024, 1) gru_seq(
    const float* __restrict__ bhh1, const float* __restrict__ bhh2)
{
    extern __shared__ unsigned char smem_raw[];
    float*  sh_h = (float*)smem_raw;
    __half* sh_w = (__half*)(smem_raw + kH * 4);

    const int blk = blockIdx.x;       // 0..127
    const int gru = blk >> 6;
    const int jbase = (blk & 63) * 32;
    const float*  __restrict__ bhh = gru ? bhh2 : bhh1;
    const float*  __restrict__ xp  = g_xp[gru];
    const __half* __restrict__ W16 = g_w16[gru];

    const int tid = threadIdx.x;
    const int w = tid >> 5, lane = tid & 31;
    const int j = jbase + w;

    // ---- preload smem weight cache: rows for j in [jbase, jbase+NCACHE) ----
    // smem layout: sh_w[(wc*3 + gate)*kH + k]
    {
        const int total_u4 = NCACHE * 3 * kH / 8;   // 13824 uint4
        uint4* d = (uint4*)sh_w;
        for (int idx = tid; idx < total_u4; idx += 1024) {
            int e   = idx * 8;
            int wc  = e / (3 * kH);
            int rem = e - wc * 3 * kH;
            int g   = rem / kH;
            int k   = rem - g * kH;
            d[idx] = *(const uint4*)(W16 + ((size_t)g * kH + (jbase + wc)) * kH + k);
        }
    }

    if (tid < 32) g_h[0][gru][jbase + tid] = 0.f;

    const float br = bhh[j], bz = bhh[kH + j], bn = bhh[2 * kH + j];
    const unsigned nblk = 64;

    grid_barrier(gru, nblk);   // also covers smem preload + h0 init visibility

    for (int t = 0; t < kT; t++) {
        const int cur = t & 1, nxt = cur ^ 1;

        // stage h into smem
        sh_h[tid]        = g_h[cur][gru][tid];
        sh_h[tid + 1024] = g_h[cur][gru][tid + 1024];
        __syncthreads();

        float xr = 0.f, xz = 0.f, xn = 0.f;
        if (lane == 0) {
            const float* xpt = xp + (size_t)t * kH3;
            xr = __ldcs(xpt + j);
            xz = __ldcs(xpt + kH + j);
            xn = __ldcs(xpt + 2 * kH + j);
        }

        float sr = 0.f, sz = 0.f, sn = 0.f;
        if (w < NCACHE) {
            dot3((const uint2*)(sh_w + (size_t)(3 * w + 0) * kH),
                 (const uint2*)(sh_w + (size_t)(3 * w + 1) * kH),
                 (const uint2*)(sh_w + (size_t)(3 * w + 2) * kH),
                 sh_h, lane, sr, sz, sn);
        } else {
            dot3((const uint2*)(W16 + ((size_t)0 * kH + j) * kH),
                 (const uint2*)(W16 + ((size_t)1 * kH + j) * kH),
                 (const uint2*)(W16 + ((size_t)2 * kH + j) * kH),
                 sh_h, lane, sr, sz, sn);
        }

        #pragma unroll
        for (int off = 16; off; off >>= 1) {
            sr += __shfl_down_sync(0xffffffffu, sr, off);
            sz += __shfl_down_sync(0xffffffffu, sz, off);
            sn += __shfl_down_sync(0xffffffffu, sn, off);
        }

        if (lane == 0) {
            float hr = sr + br, hz = sz + bz, hn = sn + bn;
            float r = 1.f / (1.f + expf(-(xr + hr)));
            float z = 1.f / (1.f + expf(-(xz + hz)));
            float n = tanhf(xn + r * hn);
            g_h[nxt][gru][j] = (1.f - z) * n + z * sh_h[j];
        }

        grid_barrier(gru, nblk);   // entry __syncthreads also protects sh_h reuse
    }
    // final h lands in g_h[0] (t=4095: cur=1 -> nxt=0)
}

// ---------------- Phase C: MLP head + log_softmax ----------------
__global__ void head_kernel(const float* __restrict__ fc1_w, const float* __restrict__ fc1_b,
                            const float* __restrict__ fc2_w, const float* __restrict__ fc2_b,
                            float* __restrict__ out)
{
    __shared__ float partial[256][4];
    __shared__ float act[256];
    __shared__ float logits[3];

    const int tid = threadIdx.x;       // 1024 threads
    const int row = tid >> 2, part = tid & 3;

    const float* hsrc = (part < 2) ? &g_h[0][0][(part & 1) * 1024]
                                   : &g_h[0][1][(part & 1) * 1024];
    const float4* wv = (const float4*)(fc1_w + (size_t)row * (2 * kH) + part * 1024);
    const float4* hv = (const float4*)hsrc;

    float s = 0.f;
    #pragma unroll 4
    for (int i = 0; i < 256; i++) {
        float4 a = wv[i], h4 = hv[i];
        s = fmaf(a.x, h4.x, s); s = fmaf(a.y, h4.y, s);
        s = fmaf(a.z, h4.z, s); s = fmaf(a.w, h4.w, s);
    }
    partial[row][part] = s;
    __syncthreads();

    if (tid < 256) {
        float v = partial[tid][0] + partial[tid][1] + partial[tid][2] + partial[tid][3]
                + fc1_b[tid];
        act[tid] = fmaxf(v, 0.f);
    }
    __syncthreads();

    if (tid < 3) {
        float s2 = fc2_b[tid];
        for (int k = 0; k < 256; k++) s2 = fmaf(fc2_w[tid * 256 + k], act[k], s2);
        logits[tid] = s2;
    }
    __syncthreads();

    if (tid == 0) {
        float m = fmaxf(logits[0], fmaxf(logits[1], logits[2]));
        float lse = m + logf(expf(logits[0] - m) + expf(logits[1] - m) + expf(logits[2] - m));
        out[0] = logits[0] - lse;
        out[1] = logits[1] - lse;
        out[2] = logits[2] - lse;
    }
}

// ---------------- launch ----------------
extern "C" void kernel_launch(void* const* d_in, const int* in_sizes, int n_in,
                              void* d_out, int out_size)
{
    const float* x1   = (const float*)d_in[0];
    const float* x2   = (const float*)d_in[1];
    const float* Wih1 = (const float*)d_in[2];
    const float* Whh1 = (const float*)d_in[3];
    const float* bih1 = (const float*)d_in[4];
    const float* bhh1 = (const float*)d_in[5];
    const float* Wih2 = (const float*)d_in[6];
    const float* Whh2 = (const float*)d_in[7];
    const float* bih2 = (const float*)d_in[8];
    const float* bhh2 = (const float*)d_in[9];
    const float* fc1w = (const float*)d_in[10];
    const float* fc1b = (const float*)d_in[11];
    const float* fc2w = (const float*)d_in[12];
    const float* fc2b = (const float*)d_in[13];
    float* out = (float*)d_out;

    cudaFuncSetAttribute(gru_seq, cudaFuncAttributeMaxDynamicSharedMemorySize, SMEM_BYTES);

    dim3 gC((unsigned)((size_t)kH3 * kH / 2 / 1024), 2);   // 6144 x 2
    convert_whh<<<gC, 1024>>>(Whh1, Whh2);

    dim3 gA(kH3 / BN, kT / BM, 2);                          // 96 x 64 x 2
    gemm_xp<<<gA, 256>>>(x1, x2, Wih1, Wih2, bih1, bih2);

    gru_seq<<<128, 1024, SMEM_BYTES>>>(bhh1, bhh2);
    head_kernel<<<1, 1024>>>(fc1w, fc1b, fc2w, fc2b, out);
}

// round 5
// speedup vs baseline: 1.8179x; 1.0820x over previous
#include <cuda_runtime.h>
#include <cuda_fp16.h>
#include <math.h>
#include <stdint.h>

// Problem dims
constexpr int kT  = 4096;   // timesteps
constexpr int kD  = 1024;   // input dim
constexpr int kH  = 2048;   // hidden
constexpr int kH3 = 3 * kH; // 6144

// GRU recurrence kernel config
constexpr int NCACHE = 18;                                   // j's per block cached in smem
constexpr int SMEM_BYTES = kH * 2 + NCACHE * 3 * kH * 2;     // 4KB h16 + 216KB w16 = 225280

// -------- scratch (static device globals; no allocation allowed) --------
__device__ float  g_xp[2][(size_t)kT * kH3];    // input projections (fp32)
__device__ __half g_w16[2][(size_t)kH3 * kH];   // fp16 W_hh
__device__ __half g_wih16[2][(size_t)kH3 * kD]; // fp16 W_ih
__device__ __half g_x16[2][(size_t)kT * kD];    // fp16 x
__device__ __half g_h16[2][2][kH];              // ping-pong hidden state (fp16) [buf][gru][H]
__device__ float  g_act[256];                   // fc1 activations
__device__ unsigned g_bar_count[2];
__device__ unsigned g_bar_gen[2];

// ---------------- per-GRU grid barrier (64 blocks, non-cooperative) ----------------
__device__ __forceinline__ void grid_barrier(int gru, unsigned nblk)
{
    __syncthreads();
    if (threadIdx.x == 0) {
        __threadfence();
        unsigned gen = *(volatile unsigned*)&g_bar_gen[gru];
        unsigned arr = atomicAdd(&g_bar_count[gru], 1u);
        if (arr == nblk - 1u) {
            g_bar_count[gru] = 0;
            __threadfence();
            atomicAdd(&g_bar_gen[gru], 1u);
        } else {
            while (*(volatile unsigned*)&g_bar_gen[gru] == gen) { __nanosleep(32); }
        }
        __threadfence();
    }
    __syncthreads();
}

// ---------------- fp32 -> fp16 conversion ----------------
// dst_id: 0/1 = W_hh1/2, 2/3 = W_ih1/2, 4/5 = x1/2
__global__ void convert_f2h(const float* __restrict__ src, int dst_id, unsigned n2)
{
    unsigned i = blockIdx.x * blockDim.x + threadIdx.x;
    if (i >= n2) return;
    __half2* dst;
    switch (dst_id) {
        case 0: dst = (__half2*)g_w16[0];   break;
        case 1: dst = (__half2*)g_w16[1];   break;
        case 2: dst = (__half2*)g_wih16[0]; break;
        case 3: dst = (__half2*)g_wih16[1]; break;
        case 4: dst = (__half2*)g_x16[0];   break;
        default: dst = (__half2*)g_x16[1];  break;
    }
    float2 v = ((const float2*)src)[i];
    dst[i] = __floats2half2_rn(v.x, v.y);
}

// ---------------- Phase A: xp = x @ W_ih^T + b_ih  (fp16 HFMA2) ----------------
constexpr int GBM = 128, GBN = 64, GBK = 32;   // t-rows, j-cols, k

__global__ void __launch_bounds__(256, 2) gemm_xp16(
    const float* __restrict__ bih1, const float* __restrict__ bih2)
{
    const int gru = blockIdx.z;
    const __half* __restrict__ X = g_x16[gru];
    const __half* __restrict__ W = g_wih16[gru];
    const float*  __restrict__ b = gru ? bih2 : bih1;
    float* __restrict__ xp = g_xp[gru];

    __shared__ __half2 As[GBK / 2][GBM + 1];   // [k2][t] padded
    __shared__ __half2 Bs[GBK / 2][GBN + 1];   // [k2][j] padded

    const int tid = threadIdx.x;            // 256
    const int tx = tid & 15, ty = tid >> 4; // j-group, t-group
    const int t0 = blockIdx.y * GBM;
    const int j0 = blockIdx.x * GBN;

    float acc[8][4] = {};

    for (int k0 = 0; k0 < kD; k0 += GBK) {
        // load A tile: 128 rows x 32 halves = 512 uint4, 2 per thread
        #pragma unroll
        for (int r = 0; r < 2; r++) {
            int i = tid + r * 256;
            int t = i >> 2;
            int kc = (i & 3) * 8;               // half offset
            uint4 v = *(const uint4*)(X + (size_t)(t0 + t) * kD + k0 + kc);
            const __half2* hv = (const __half2*)&v;
            int k2b = kc >> 1;
            As[k2b + 0][t] = hv[0]; As[k2b + 1][t] = hv[1];
            As[k2b + 2][t] = hv[2]; As[k2b + 3][t] = hv[3];
        }
        // load B tile: 64 rows x 32 halves = 256 uint4, 1 per thread
        {
            int j = tid >> 2;
            int kc = (tid & 3) * 8;
            uint4 v = *(const uint4*)(W + (size_t)(j0 + j) * kD + k0 + kc);
            const __half2* hv = (const __half2*)&v;
            int k2b = kc >> 1;
            Bs[k2b + 0][j] = hv[0]; Bs[k2b + 1][j] = hv[1];
            Bs[k2b + 2][j] = hv[2]; Bs[k2b + 3][j] = hv[3];
        }
        __syncthreads();

        __half2 hz = __float2half2_rn(0.f);
        __half2 hacc[8][4];
        #pragma unroll
        for (int i = 0; i < 8; i++)
            #pragma unroll
            for (int l = 0; l < 4; l++) hacc[i][l] = hz;

        #pragma unroll
        for (int k2 = 0; k2 < GBK / 2; k2++) {
            __half2 a[8], bb[4];
            #pragma unroll
            for (int i = 0; i < 8; i++) a[i] = As[k2][ty * 8 + i];
            #pragma unroll
            for (int l = 0; l < 4; l++) bb[l] = Bs[k2][tx * 4 + l];
            #pragma unroll
            for (int i = 0; i < 8; i++)
                #pragma unroll
                for (int l = 0; l < 4; l++)
                    hacc[i][l] = __hfma2(a[i], bb[l], hacc[i][l]);
        }
        // flush fp16 partials into fp32 accumulators (per k-tile)
        #pragma unroll
        for (int i = 0; i < 8; i++)
            #pragma unroll
            for (int l = 0; l < 4; l++) {
                float2 f = __half22float2(hacc[i][l]);
                acc[i][l] += f.x + f.y;
            }
        __syncthreads();
    }

    const int jj = j0 + tx * 4;
    float4 bv = *(const float4*)(b + jj);
    #pragma unroll
    for (int i = 0; i < 8; i++) {
        float4 v = make_float4(acc[i][0] + bv.x, acc[i][1] + bv.y,
                               acc[i][2] + bv.z, acc[i][3] + bv.w);
        __stcs((float4*)(xp + (size_t)(t0 + ty * 8 + i) * kH3 + jj), v);
    }
}

// ---------------- gru dot helpers (HFMA2, chunked fp16 accumulate) ----------------
__device__ __forceinline__ float gatedot(const uint4* __restrict__ w,
                                         const uint4 hh[4], int lane)
{
    float s = 0.f;
    #pragma unroll
    for (int i = 0; i < 4; i++) {
        uint4 wv = w[i * 32 + lane];
        __half2 acc = __hmul2(*(const __half2*)&wv.x, *(const __half2*)&hh[i].x);
        acc = __hfma2(*(const __half2*)&wv.y, *(const __half2*)&hh[i].y, acc);
        acc = __hfma2(*(const __half2*)&wv.z, *(const __half2*)&hh[i].z, acc);
        acc = __hfma2(*(const __half2*)&wv.w, *(const __half2*)&hh[i].w, acc);
        float2 f = __half22float2(acc);
        s += f.x + f.y;
    }
    return s;
}

__device__ __forceinline__ void dot3h(const uint4* __restrict__ w0,
                                      const uint4* __restrict__ w1,
                                      const uint4* __restrict__ w2,
                                      const uint4* __restrict__ hv4, int lane,
                                      float& sr, float& sz, float& sn)
{
    #pragma unroll
    for (int hf = 0; hf < 2; hf++) {
        uint4 hh[4];
        #pragma unroll
        for (int i = 0; i < 4; i++) hh[i] = hv4[hf * 128 + i * 32 + lane];
        sr += gatedot(w0 + hf * 128, hh, lane);
        sz += gatedot(w1 + hf * 128, hh, lane);
        sn += gatedot(w2 + hf * 128, hh, lane);
    }
}

// ---------------- Phase B: persistent GRU recurrence ----------------
__global__ void __launch_bounds__(1024, 1) gru_seq(
    const float* __restrict__ bhh1, const float* __restrict__ bhh2)
{
    extern __shared__ unsigned char smem_raw[];
    __half* sh_h16 = (__half*)smem_raw;                 // 2048 halves
    __half* sh_w   = (__half*)(smem_raw + kH * 2);      // NCACHE*3*2048 halves

    const int blk = blockIdx.x;       // 0..127
    const int gru = blk >> 6;
    const int jbase = (blk & 63) * 32;
    const float*  __restrict__ bhh = gru ? bhh2 : bhh1;
    const float*  __restrict__ xp  = g_xp[gru];
    const __half* __restrict__ W16 = g_w16[gru];

    const int tid = threadIdx.x;
    const int w = tid >> 5, lane = tid & 31;
    const int j = jbase + w;

    // preload smem weight cache: rows for j in [jbase, jbase+NCACHE)
    {
        const int total_u4 = NCACHE * 3 * kH / 8;
        uint4* d = (uint4*)sh_w;
        for (int idx = tid; idx < total_u4; idx += 1024) {
            int e   = idx * 8;
            int wc  = e / (3 * kH);
            int rem = e - wc * 3 * kH;
            int g   = rem / kH;
            int k   = rem - g * kH;
            d[idx] = *(const uint4*)(W16 + ((size_t)g * kH + (jbase + wc)) * kH + k);
        }
    }

    if (tid < 32) g_h16[0][gru][jbase + tid] = __float2half(0.f);

    const float br = bhh[j], bz = bhh[kH + j], bn = bhh[2 * kH + j];
    float h_prev = 0.f;                                 // lane 0's fp32 h[j]

    const bool cached = (w < NCACHE);
    const uint4* wp0; const uint4* wp1; const uint4* wp2;
    if (cached) {
        wp0 = (const uint4*)(sh_w + (size_t)(3 * w + 0) * kH);
        wp1 = (const uint4*)(sh_w + (size_t)(3 * w + 1) * kH);
        wp2 = (const uint4*)(sh_w + (size_t)(3 * w + 2) * kH);
    } else {
        wp0 = (const uint4*)(W16 + ((size_t)0 * kH + j) * kH);
        wp1 = (const uint4*)(W16 + ((size_t)1 * kH + j) * kH);
        wp2 = (const uint4*)(W16 + ((size_t)2 * kH + j) * kH);
    }

    grid_barrier(gru, 64);   // covers smem preload + h0 init

    for (int t = 0; t < kT; t++) {
        const int cur = t & 1, nxt = cur ^ 1;

        // stage h (fp16) into smem: 1024 uint32
        ((unsigned*)sh_h16)[tid] = ((const unsigned*)g_h16[cur][gru])[tid];
        __syncthreads();

        float xr = 0.f, xz = 0.f, xn = 0.f;
        if (lane == 0) {
            const float* xpt = xp + (size_t)t * kH3;
            xr = __ldcs(xpt + j);
            xz = __ldcs(xpt + kH + j);
            xn = __ldcs(xpt + 2 * kH + j);
        }

        float sr = 0.f, sz = 0.f, sn = 0.f;
        dot3h(wp0, wp1, wp2, (const uint4*)sh_h16, lane, sr, sz, sn);

        #pragma unroll
        for (int off = 16; off; off >>= 1) {
            sr += __shfl_down_sync(0xffffffffu, sr, off);
            sz += __shfl_down_sync(0xffffffffu, sz, off);
            sn += __shfl_down_sync(0xffffffffu, sn, off);
        }

        if (lane == 0) {
            float hr = sr + br, hz = sz + bz, hn = sn + bn;
            float r = 1.f / (1.f + expf(-(xr + hr)));
            float z = 1.f / (1.f + expf(-(xz + hz)));
            float n = tanhf(xn + r * hn);
            float hnew = (1.f - z) * n + z * h_prev;
            h_prev = hnew;
            g_h16[nxt][gru][j] = __float2half(hnew);
        }

        grid_barrier(gru, 64);
    }
    // final h in g_h16[0]
}

// ---------------- Phase C1: fc1 (parallel over 32 blocks) ----------------
__global__ void head_fc1(const float* __restrict__ fc1_w, const float* __restrict__ fc1_b)
{
    const int r = blockIdx.x * 8 + (threadIdx.x >> 5);   // 32 blocks x 8 warps = 256 rows
    const int lane = threadIdx.x & 31;
    const __half* __restrict__ h0 = g_h16[0][0];
    const __half* __restrict__ h1 = g_h16[0][1];
    const float* __restrict__ wr = fc1_w + (size_t)r * (2 * kH);

    float s = 0.f;
    #pragma unroll 4
    for (int i = 0; i < 32; i++) {
        int k = i * 128 + lane * 4;
        float4 wv = *(const float4*)(wr + k);
        const __half* hs = (k < kH) ? (h0 + k) : (h1 + (k - kH));
        uint2 hh = *(const uint2*)hs;
        float2 f0 = __half22float2(*(const __half2*)&hh.x);
        float2 f1 = __half22float2(*(const __half2*)&hh.y);
        s = fmaf(wv.x, f0.x, s); s = fmaf(wv.y, f0.y, s);
        s = fmaf(wv.z, f1.x, s); s = fmaf(wv.w, f1.y, s);
    }
    #pragma unroll
    for (int off = 16; off; off >>= 1) s += __shfl_down_sync(0xffffffffu, s, off);
    if (lane == 0) g_act[r] = fmaxf(s + fc1_b[r], 0.f);
}

// ---------------- Phase C2: fc2 + log_softmax ----------------
__global__ void head_fc2(const float* __restrict__ fc2_w, const float* __restrict__ fc2_b,
                         float* __restrict__ out)
{
    __shared__ float logits[3];
    const int g = threadIdx.x >> 5, lane = threadIdx.x & 31;   // 96 threads, 3 warps
    float s = 0.f;
    const float* wr = fc2_w + g * 256;
    #pragma unroll
    for (int i = 0; i < 2; i++) {
        int k = lane * 8 + i * 4;      // lane covers 8 els
        float4 wv = *(const float4*)(wr + k);
        float4 av = *(const float4*)(g_act + k);
        s = fmaf(wv.x, av.x, s); s = fmaf(wv.y, av.y, s);
        s = fmaf(wv.z, av.z, s); s = fmaf(wv.w, av.w, s);
    }
    #pragma unroll
    for (int off = 16; off; off >>= 1) s += __shfl_down_sync(0xffffffffu, s, off);
    if (lane == 0) logits[g] = s + fc2_b[g];
    __syncthreads();
    if (threadIdx.x == 0) {
        float m = fmaxf(logits[0], fmaxf(logits[1], logits[2]));
        float lse = m + logf(expf(logits[0] - m) + expf(logits[1] - m) + expf(logits[2] - m));
        out[0] = logits[0] - lse;
        out[1] = logits[1] - lse;
        out[2] = logits[2] - lse;
    }
}

// ---------------- launch ----------------
extern "C" void kernel_launch(void* const* d_in, const int* in_sizes, int n_in,
                              void* d_out, int out_size)
{
    const float* x1   = (const float*)d_in[0];
    const float* x2   = (const float*)d_in[1];
    const float* Wih1 = (const float*)d_in[2];
    const float* Whh1 = (const float*)d_in[3];
    const float* bih1 = (const float*)d_in[4];
    const float* bhh1 = (const float*)d_in[5];
    const float* Wih2 = (const float*)d_in[6];
    const float* Whh2 = (const float*)d_in[7];
    const float* bih2 = (const float*)d_in[8];
    const float* bhh2 = (const float*)d_in[9];
    const float* fc1w = (const float*)d_in[10];
    const float* fc1b = (const float*)d_in[11];
    const float* fc2w = (const float*)d_in[12];
    const float* fc2b = (const float*)d_in[13];
    float* out = (float*)d_out;

    cudaFuncSetAttribute(gru_seq, cudaFuncAttributeMaxDynamicSharedMemorySize, SMEM_BYTES);

    // fp32 -> fp16 conversions
    const unsigned nWhh = kH3 * kH / 2, nWih = kH3 * kD / 2, nX = kT * kD / 2;
    convert_f2h<<<(nWhh + 1023) / 1024, 1024>>>(Whh1, 0, nWhh);
    convert_f2h<<<(nWhh + 1023) / 1024, 1024>>>(Whh2, 1, nWhh);
    convert_f2h<<<(nWih + 1023) / 1024, 1024>>>(Wih1, 2, nWih);
    convert_f2h<<<(nWih + 1023) / 1024, 1024>>>(Wih2, 3, nWih);
    convert_f2h<<<(nX   + 1023) / 1024, 1024>>>(x1,   4, nX);
    convert_f2h<<<(nX   + 1023) / 1024, 1024>>>(x2,   5, nX);

    dim3 gA(kH3 / GBN, kT / GBM, 2);   // 96 x 32 x 2
    gemm_xp16<<<gA, 256>>>(bih1, bih2);

    gru_seq<<<128, 1024, SMEM_BYTES>>>(bhh1, bhh2);

    head_fc1<<<32, 256>>>(fc1w, fc1b);
    head_fc2<<<1, 96>>>(fc2w, fc2b, out);
}

// round 6
// speedup vs baseline: 1.9475x; 1.0713x over previous
#include <cuda_runtime.h>
#include <cuda_fp16.h>
#include <math.h>
#include <stdint.h>

// Problem dims
constexpr int kT  = 4096;   // timesteps
constexpr int kD  = 1024;   // input dim
constexpr int kH  = 2048;   // hidden
constexpr int kH3 = 3 * kH; // 6144

// GRU recurrence kernel config
constexpr int NCACHE = 18;                                   // j's per block cached in smem
constexpr int SMEM_BYTES = kH * 2 + NCACHE * 3 * kH * 2;     // 4KB h16 + 216KB w16 = 225280

// -------- scratch (static device globals; no allocation allowed) --------
__device__ float  g_xp[2][(size_t)kT * kH3];    // input projections (fp32)
__device__ __half g_w16[2][(size_t)kH3 * kH];   // fp16 W_hh
__device__ __half g_wih16[2][(size_t)kH3 * kD]; // fp16 W_ih
__device__ __half g_x16[2][(size_t)kT * kD];    // fp16 x
__device__ __half g_h16[2][2][kH];              // ping-pong hidden state [buf][gru][H]
__device__ float  g_act[256];                   // fc1 activations
__device__ unsigned g_bar_count[2];
__device__ unsigned g_bar_gen[2];

// ---------------- per-GRU grid barrier (64 blocks, non-cooperative) ----------------
__device__ __forceinline__ void grid_barrier(int gru, unsigned nblk)
{
    __syncthreads();
    if (threadIdx.x == 0) {
        __threadfence();
        unsigned gen = *(volatile unsigned*)&g_bar_gen[gru];
        unsigned arr = atomicAdd(&g_bar_count[gru], 1u);
        if (arr == nblk - 1u) {
            g_bar_count[gru] = 0;
            __threadfence();
            atomicAdd(&g_bar_gen[gru], 1u);
        } else {
            while (*(volatile unsigned*)&g_bar_gen[gru] == gen) {}
        }
        __threadfence();
    }
    __syncthreads();
}

// ---------------- fp32 -> fp16 conversions (launch-count matters: gru must be idx 5) --
__global__ void convert_whh(const float* __restrict__ src, int gru)
{
    const size_t i = (size_t)blockIdx.x * blockDim.x + threadIdx.x;   // kH3*kH/2 = 6144*1024
    float2 v = ((const float2*)src)[i];
    ((__half2*)g_w16[gru])[i] = __floats2half2_rn(v.x, v.y);
}
__global__ void convert_wih2(const float* __restrict__ W1, const float* __restrict__ W2)
{
    const size_t i = (size_t)blockIdx.x * blockDim.x + threadIdx.x;   // kH3*kD/2
    const float2* src = (const float2*)(blockIdx.y ? W2 : W1);
    float2 v = src[i];
    ((__half2*)g_wih16[blockIdx.y])[i] = __floats2half2_rn(v.x, v.y);
}
__global__ void convert_x2(const float* __restrict__ x1, const float* __restrict__ x2)
{
    const size_t i = (size_t)blockIdx.x * blockDim.x + threadIdx.x;   // kT*kD/2
    const float2* src = (const float2*)(blockIdx.y ? x2 : x1);
    float2 v = src[i];
    ((__half2*)g_x16[blockIdx.y])[i] = __floats2half2_rn(v.x, v.y);
}

// ---------------- Phase A: xp = x @ W_ih^T + b_ih  (fp16 HFMA2) ----------------
constexpr int GBM = 128, GBN = 64, GBK = 32;

__global__ void __launch_bounds__(256, 2) gemm_xp16(
    const float* __restrict__ bih1, const float* __restrict__ bih2)
{
    const int gru = blockIdx.z;
    const __half* __restrict__ X = g_x16[gru];
    const __half* __restrict__ W = g_wih16[gru];
    const float*  __restrict__ b = gru ? bih2 : bih1;
    float* __restrict__ xp = g_xp[gru];

    __shared__ __half2 As[GBK / 2][GBM + 1];
    __shared__ __half2 Bs[GBK / 2][GBN + 1];

    const int tid = threadIdx.x;
    const int tx = tid & 15, ty = tid >> 4;
    const int t0 = blockIdx.y * GBM;
    const int j0 = blockIdx.x * GBN;

    float acc[8][4] = {};

    for (int k0 = 0; k0 < kD; k0 += GBK) {
        #pragma unroll
        for (int r = 0; r < 2; r++) {
            int i = tid + r * 256;
            int t = i >> 2;
            int kc = (i & 3) * 8;
            uint4 v = *(const uint4*)(X + (size_t)(t0 + t) * kD + k0 + kc);
            const __half2* hv = (const __half2*)&v;
            int k2b = kc >> 1;
            As[k2b + 0][t] = hv[0]; As[k2b + 1][t] = hv[1];
            As[k2b + 2][t] = hv[2]; As[k2b + 3][t] = hv[3];
        }
        {
            int j = tid >> 2;
            int kc = (tid & 3) * 8;
            uint4 v = *(const uint4*)(W + (size_t)(j0 + j) * kD + k0 + kc);
            const __half2* hv = (const __half2*)&v;
            int k2b = kc >> 1;
            Bs[k2b + 0][j] = hv[0]; Bs[k2b + 1][j] = hv[1];
            Bs[k2b + 2][j] = hv[2]; Bs[k2b + 3][j] = hv[3];
        }
        __syncthreads();

        __half2 hz = __float2half2_rn(0.f);
        __half2 hacc[8][4];
        #pragma unroll
        for (int i = 0; i < 8; i++)
            #pragma unroll
            for (int l = 0; l < 4; l++) hacc[i][l] = hz;

        #pragma unroll
        for (int k2 = 0; k2 < GBK / 2; k2++) {
            __half2 a[8], bb[4];
            #pragma unroll
            for (int i = 0; i < 8; i++) a[i] = As[k2][ty * 8 + i];
            #pragma unroll
            for (int l = 0; l < 4; l++) bb[l] = Bs[k2][tx * 4 + l];
            #pragma unroll
            for (int i = 0; i < 8; i++)
                #pragma unroll
                for (int l = 0; l < 4; l++)
                    hacc[i][l] = __hfma2(a[i], bb[l], hacc[i][l]);
        }
        #pragma unroll
        for (int i = 0; i < 8; i++)
            #pragma unroll
            for (int l = 0; l < 4; l++) {
                float2 f = __half22float2(hacc[i][l]);
                acc[i][l] += f.x + f.y;
            }
        __syncthreads();
    }

    const int jj = j0 + tx * 4;
    float4 bv = *(const float4*)(b + jj);
    #pragma unroll
    for (int i = 0; i < 8; i++) {
        float4 v = make_float4(acc[i][0] + bv.x, acc[i][1] + bv.y,
                               acc[i][2] + bv.z, acc[i][3] + bv.w);
        __stcs((float4*)(xp + (size_t)(t0 + ty * 8 + i) * kH3 + jj), v);
    }
}

// ---------------- row FMA: 8-chunk fp16 accumulate, fp32 flush per chunk -------------
__device__ __forceinline__ float fma_row(const uint4 wv[8], const uint4 hh[8])
{
    float s = 0.f;
    #pragma unroll
    for (int i = 0; i < 8; i++) {
        __half2 t = __hmul2(*(const __half2*)&wv[i].x, *(const __half2*)&hh[i].x);
        t = __hfma2(*(const __half2*)&wv[i].y, *(const __half2*)&hh[i].y, t);
        t = __hfma2(*(const __half2*)&wv[i].z, *(const __half2*)&hh[i].z, t);
        t = __hfma2(*(const __half2*)&wv[i].w, *(const __half2*)&hh[i].w, t);
        float2 f = __half22float2(t);
        s += f.x + f.y;
    }
    return s;
}

// ---------------- Phase B: persistent GRU recurrence ----------------
// 128 blocks x 512 threads (16 warps). Block owns 32 j's; warp w owns j = 2w, 2w+1.
// Warps 0..8 (j 0..17): weight rows in smem. Warps 9..15 (j 18..31): streamed from L2
// with deep explicit MLP (16 LDG.128 in flight per gate-pair, issued before h is read).
__global__ void __launch_bounds__(512, 1) gru_seq(
    const float* __restrict__ bhh1, const float* __restrict__ bhh2)
{
    extern __shared__ unsigned char smem_raw[];
    __half* sh_h = (__half*)smem_raw;                 // 2048 halves
    __half* sh_w = (__half*)(smem_raw + kH * 2);      // NCACHE*3*2048 halves

    const int blk = blockIdx.x;       // 0..127
    const int gru = blk >> 6;
    const int jbase = (blk & 63) * 32;
    const float*  __restrict__ bhh = gru ? bhh2 : bhh1;
    const float*  __restrict__ xp  = g_xp[gru];
    const __half* __restrict__ W16 = g_w16[gru];

    const int tid = threadIdx.x;
    const int w = tid >> 5, lane = tid & 31;
    const int jlo = jbase + 2 * w;          // this warp's two hidden units
    const int jm  = (lane >= 16) ? (jlo + 1) : jlo;   // lane 0 -> jlo, lane 16 -> jhi

    // preload smem weight cache: rows for j in [jbase, jbase+NCACHE)
    {
        const int total_u4 = NCACHE * 3 * kH / 8;     // 13824
        uint4* d = (uint4*)sh_w;
        for (int idx = tid; idx < total_u4; idx += 512) {
            int e   = idx * 8;
            int wc  = e / (3 * kH);
            int rem = e - wc * 3 * kH;
            int g   = rem / kH;
            int k   = rem - g * kH;
            d[idx] = *(const uint4*)(W16 + ((size_t)g * kH + (jbase + wc)) * kH + k);
        }
    }

    if (tid < 32) g_h16[0][gru][jbase + tid] = __float2half(0.f);

    const float br = bhh[jm], bz = bhh[kH + jm], bn = bhh[2 * kH + jm];
    float h_prev = 0.f;                    // lanes 0/16: fp32 h[jm]

    const bool cached = (w < 9);           // 2w+1 <= 17 < NCACHE
    // row base pointers (gate g row = base + g*stride)
    const uint4* cLo = (const uint4*)(sh_w + (size_t)(2 * w) * 3 * kH);         // cached
    const uint4* gLo = (const uint4*)(W16 + (size_t)jlo * kH);                   // streamed
    const size_t cG = kH / 8;              // uint4 stride between gates (cached rows adjacent)
    const size_t gG = (size_t)kH * kH / 8; // uint4 stride between gate blocks (gmem)
    const size_t cHi = 3 * kH / 8;         // jhi offset (cached)
    const size_t gHi = kH / 8;             // jhi offset (gmem)

    grid_barrier(gru, 64);   // covers smem preload + h0 init

    const uint4* hv = (const uint4*)sh_h;

    for (int t = 0; t < kT; t++) {
        const int cur = t & 1, nxt = cur ^ 1;

        // stage h (fp16) into smem: 512 x uint2 = 4096 B
        ((uint2*)sh_h)[tid] = ((const uint2*)g_h16[cur][gru])[tid];

        // xp for my j (only lanes 0/16 need it)
        float xr = 0.f, xz = 0.f, xn = 0.f;
        if ((lane & 15) == 0) {
            const float* xpt = xp + (size_t)t * kH3;
            xr = __ldcs(xpt + jm);
            xz = __ldcs(xpt + kH + jm);
            xn = __ldcs(xpt + 2 * kH + jm);
        }

        float s[6];   // [0..2]=jlo r,z,n   [3..5]=jhi r,z,n

        if (cached) {
            __syncthreads();
            uint4 hh[8];
            #pragma unroll
            for (int i = 0; i < 8; i++) hh[i] = hv[i * 32 + lane];
            #pragma unroll
            for (int g = 0; g < 3; g++) {
                uint4 av[8], bv[8];
                const uint4* A = cLo + g * cG;
                const uint4* B = A + cHi;
                #pragma unroll
                for (int i = 0; i < 8; i++) av[i] = A[i * 32 + lane];
                #pragma unroll
                for (int i = 0; i < 8; i++) bv[i] = B[i * 32 + lane];
                s[g]     = fma_row(av, hh);
                s[3 + g] = fma_row(bv, hh);
            }
        } else {
            // issue gate-0 weight loads BEFORE consuming h (no dependency)
            uint4 av[8], bv[8];
            {
                const uint4* A = gLo;            // gate 0 jlo
                const uint4* B = gLo + gHi;      // gate 0 jhi
                #pragma unroll
                for (int i = 0; i < 8; i++) av[i] = __ldcg(A + i * 32 + lane);
                #pragma unroll
                for (int i = 0; i < 8; i++) bv[i] = __ldcg(B + i * 32 + lane);
            }
            __syncthreads();
            uint4 hh[8];
            #pragma unroll
            for (int i = 0; i < 8; i++) hh[i] = hv[i * 32 + lane];

            s[0] = fma_row(av, hh);
            s[3] = fma_row(bv, hh);
            #pragma unroll
            for (int g = 1; g < 3; g++) {
                const uint4* A = gLo + g * gG;
                const uint4* B = A + gHi;
                #pragma unroll
                for (int i = 0; i < 8; i++) av[i] = __ldcg(A + i * 32 + lane);
                #pragma unroll
                for (int i = 0; i < 8; i++) bv[i] = __ldcg(B + i * 32 + lane);
                s[g]     = fma_row(av, hh);
                s[3 + g] = fma_row(bv, hh);
            }
        }

        // butterfly reduce all 6 sums (result valid in every lane)
        #pragma unroll
        for (int off = 16; off; off >>= 1)
            #pragma unroll
            for (int q = 0; q < 6; q++)
                s[q] += __shfl_xor_sync(0xffffffffu, s[q], off);

        if ((lane & 15) == 0) {
            const int sel = (lane >> 4) * 3;    // 0 for jlo, 3 for jhi
            float hr = s[sel + 0] + br, hz = s[sel + 1] + bz, hn = s[sel + 2] + bn;
            float r = 1.f / (1.f + expf(-(xr + hr)));
            float z = 1.f / (1.f + expf(-(xz + hz)));
            float n = tanhf(xn + r * hn);
            float hnew = (1.f - z) * n + z * h_prev;
            h_prev = hnew;
            g_h16[nxt][gru][jm] = __float2half(hnew);
        }

        grid_barrier(gru, 64);
    }
    // final h in g_h16[0]
}

// ---------------- Phase C1: fc1 (parallel over 32 blocks) ----------------
__global__ void head_fc1(const float* __restrict__ fc1_w, const float* __restrict__ fc1_b)
{
    const int r = blockIdx.x * 8 + (threadIdx.x >> 5);
    const int lane = threadIdx.x & 31;
    const __half* __restrict__ h0 = g_h16[0][0];
    const __half* __restrict__ h1 = g_h16[0][1];
    const float* __restrict__ wr = fc1_w + (size_t)r * (2 * kH);

    float s = 0.f;
    #pragma unroll 4
    for (int i = 0; i < 32; i++) {
        int k = i * 128 + lane * 4;
        float4 wv = *(const float4*)(wr + k);
        const __half* hs = (k < kH) ? (h0 + k) : (h1 + (k - kH));
        uint2 hh = *(const uint2*)hs;
        float2 f0 = __half22float2(*(const __half2*)&hh.x);
        float2 f1 = __half22float2(*(const __half2*)&hh.y);
        s = fmaf(wv.x, f0.x, s); s = fmaf(wv.y, f0.y, s);
        s = fmaf(wv.z, f1.x, s); s = fmaf(wv.w, f1.y, s);
    }
    #pragma unroll
    for (int off = 16; off; off >>= 1) s += __shfl_down_sync(0xffffffffu, s, off);
    if (lane == 0) g_act[r] = fmaxf(s + fc1_b[r], 0.f);
}

// ---------------- Phase C2: fc2 + log_softmax ----------------
__global__ void head_fc2(const float* __restrict__ fc2_w, const float* __restrict__ fc2_b,
                         float* __restrict__ out)
{
    __shared__ float logits[3];
    const int g = threadIdx.x >> 5, lane = threadIdx.x & 31;
    float s = 0.f;
    const float* wr = fc2_w + g * 256;
    #pragma unroll
    for (int i = 0; i < 2; i++) {
        int k = lane * 8 + i * 4;
        float4 wv = *(const float4*)(wr + k);
        float4 av = *(const float4*)(g_act + k);
        s = fmaf(wv.x, av.x, s); s = fmaf(wv.y, av.y, s);
        s = fmaf(wv.z, av.z, s); s = fmaf(wv.w, av.w, s);
    }
    #pragma unroll
    for (int off = 16; off; off >>= 1) s += __shfl_down_sync(0xffffffffu, s, off);
    if (lane == 0) logits[g] = s + fc2_b[g];
    __syncthreads();
    if (threadIdx.x == 0) {
        float m = fmaxf(logits[0], fmaxf(logits[1], logits[2]));
        float lse = m + logf(expf(logits[0] - m) + expf(logits[1] - m) + expf(logits[2] - m));
        out[0] = logits[0] - lse;
        out[1] = logits[1] - lse;
        out[2] = logits[2] - lse;
    }
}

// ---------------- launch (gru_seq must be launch index 5 for ncu -s 5) ----------------
extern "C" void kernel_launch(void* const* d_in, const int* in_sizes, int n_in,
                              void* d_out, int out_size)
{
    const float* x1   = (const float*)d_in[0];
    const float* x2   = (const float*)d_in[1];
    const float* Wih1 = (const float*)d_in[2];
    const float* Whh1 = (const float*)d_in[3];
    const float* bih1 = (const float*)d_in[4];
    const float* bhh1 = (const float*)d_in[5];
    const float* Wih2 = (const float*)d_in[6];
    const float* Whh2 = (const float*)d_in[7];
    const float* bih2 = (const float*)d_in[8];
    const float* bhh2 = (const float*)d_in[9];
    const float* fc1w = (const float*)d_in[10];
    const float* fc1b = (const float*)d_in[11];
    const float* fc2w = (const float*)d_in[12];
    const float* fc2b = (const float*)d_in[13];
    float* out = (float*)d_out;

    cudaFuncSetAttribute(gru_seq, cudaFuncAttributeMaxDynamicSharedMemorySize, SMEM_BYTES);

    convert_whh<<<kH3 * kH / 2 / 1024, 1024>>>(Whh1, 0);              // launch 0
    convert_whh<<<kH3 * kH / 2 / 1024, 1024>>>(Whh2, 1);              // launch 1
    convert_wih2<<<dim3(kH3 * kD / 2 / 1024, 2), 1024>>>(Wih1, Wih2); // launch 2
    convert_x2<<<dim3(kT * kD / 2 / 1024, 2), 1024>>>(x1, x2);        // launch 3

    dim3 gA(kH3 / GBN, kT / GBM, 2);
    gemm_xp16<<<gA, 256>>>(bih1, bih2);                               // launch 4

    gru_seq<<<128, 512, SMEM_BYTES>>>(bhh1, bhh2);                    // launch 5 (profiled)

    head_fc1<<<32, 256>>>(fc1w, fc1b);
    head_fc2<<<1, 96>>>(fc2w, fc2b, out);
}